// round 11
// baseline (speedup 1.0000x reference)
#include <cuda_runtime.h>
#include <math.h>

#define BATCH 8
#define NPTS  2000
#define CDIM  128
#define KNN   9
#define PTOT  (BATCH*NPTS)   // 16000

// ---------------- scratch (device globals; no allocations allowed) ----------------
__device__ int   g_idx1[PTOT*KNN];
__device__ int   g_idx2[PTOT*KNN];
__device__ float g_sqx[PTOT];
__device__ float g_sqm[PTOT];
__device__ float g_W[128*512];        // packed conv1 weights, layout [k][512]
__device__ float g_W2t[384*128];      // conv2 weights transposed, layout [j][128]
__device__ float g_P[PTOT*512];       // per-point precomputed features [p][512]
__device__ float g_y1[PTOT*384];      // conv1 output (pre-BN) [p][w*128+c]
__device__ float g_y2a[PTOT*128];     // conv2 output branch1 (pre-BN)
__device__ float g_y2b[PTOT*128];     // conv2 output branch2 (pre-BN)
__device__ float g_part[2*256*128];   // stats partials
__device__ float g_st1[256];          // [sum(128), sumsq(128)]
__device__ float g_st2a[256];
__device__ float g_st2b[256];

// ---------------- squared norms: XLA column-reduce shape (stride-32 tree) ----------------
__global__ void sq_kernel(const float* __restrict__ x, float* __restrict__ sq) {
    int w = (blockIdx.x * blockDim.x + threadIdx.x) >> 5;   // point index
    int lane = threadIdx.x & 31;
    if (w >= PTOT) return;
    int b = w / NPTS;
    int n = w - b * NPTS;
    const float* px = x + ((size_t)b * CDIM) * NPTS + n;
    float p = 0.f;
    #pragma unroll
    for (int k = 0; k < 4; ++k) {
        float v = px[(size_t)(lane + 32*k) * NPTS];
        p = fmaf(v, v, p);
    }
    #pragma unroll
    for (int off = 16; off; off >>= 1)
        p = __fadd_rn(p, __shfl_down_sync(0xffffffffu, p, off));
    if (lane == 0) sq[w] = p;
}

// ---------------- fused pairwise-distance + top-9 ----------------
// 256 threads/block: thread = (row r, half h). Half h processes column tiles
// 2*tp+h (32 cols each) with its own top-9 list; final smem merge of the two
// sorted lists. Comparator (LOCKED, matches XLA TopK):
//   value desc, then rev6(j mod 64) asc, then j asc.
// Inner product: single serial ascending FFMA chain per output (LOCKED).
// grid (16, B), block 256. dyn smem: rs[128*128] + cs[2*128*32] + csq[64]
__global__ void knn_kernel(const float* __restrict__ x, const float* __restrict__ sq,
                           int* __restrict__ out_idx) {
    extern __shared__ float sm[];
    float* rs  = sm;                 // [d][r] transposed rows, 16384 floats
    float* cs  = sm + 128*128;       // [t][d][c], 2*4096 floats
    float* csq = cs + 2*128*32;      // 64

    const int b   = blockIdx.y;
    const int n0  = blockIdx.x * 128;
    const int tid = threadIdx.x;
    const int r   = tid & 127;
    const int h   = tid >> 7;        // 0 or 1
    const int row = n0 + r;

    // load row tile transposed: rs[d*128 + rr] = x[b][d][n0+rr]
    for (int i = tid; i < 128*128; i += 256) {
        int d = i >> 7, rr = i & 127;
        int n = n0 + rr;
        rs[i] = (n < NPTS) ? x[(b*CDIM + d)*NPTS + n] : 0.f;
    }

    float tv[KNN]; int ti[KNN]; unsigned tr[KNN];
    #pragma unroll
    for (int q = 0; q < KNN; ++q) { tv[q] = -3.402823e38f; ti[q] = 0; tr[q] = 0xffffffffu; }

    const float sqr = (row < NPTS) ? sq[b*NPTS + row] : 0.f;

    for (int tp = 0; tp < 32; ++tp) {       // tile pair: tiles 2*tp and 2*tp+1
        __syncthreads();
        for (int i = tid; i < 2*128*32; i += 256) {
            int t = i >> 12;                 // 0/1
            int d = (i >> 5) & 127;
            int c = i & 31;
            int n = (2*tp + t)*32 + c;
            cs[i] = (n < NPTS) ? x[(b*CDIM + d)*NPTS + n] : 0.f;
        }
        if (tid < 64) {
            int t = tid >> 5;
            int n = (2*tp + t)*32 + (tid & 31);
            csq[tid] = (n < NPTS) ? sq[b*NPTS + n] : 0.f;
        }
        __syncthreads();

        const int c0 = (2*tp + h)*32;
        if (c0 >= NPTS) continue;

        float acc[32];
        #pragma unroll
        for (int c = 0; c < 32; ++c) acc[c] = 0.f;

        const float4* cs4 = (const float4*)(cs + h*128*32);
        #pragma unroll 4
        for (int d = 0; d < 128; ++d) {
            float rv = rs[d*128 + r];
            #pragma unroll
            for (int c8 = 0; c8 < 8; ++c8) {
                float4 q4 = cs4[d*8 + c8];
                acc[c8*4+0] = fmaf(rv, q4.x, acc[c8*4+0]);
                acc[c8*4+1] = fmaf(rv, q4.y, acc[c8*4+1]);
                acc[c8*4+2] = fmaf(rv, q4.z, acc[c8*4+2]);
                acc[c8*4+3] = fmaf(rv, q4.w, acc[c8*4+3]);
            }
        }

        const float* csqh = csq + h*32;
        #pragma unroll
        for (int c = 0; c < 32; ++c) {
            if (c0 + c < NPTS) {
                // LOCKED rounding: fmaf(2,acc,-sqr) == RN(2*acc - sqr)
                float v = __fadd_rn(fmaf(2.f, acc[c], -sqr), -csqh[c]);
                int jn = c0 + c;
                unsigned rk = __brev((unsigned)(jn & 63)) >> 26;   // rev6(thread id)
                bool bl = (v > tv[KNN-1]) || (v == tv[KNN-1] && rk < tr[KNN-1]);
                if (bl) {
                    int pos = KNN-1;
                    #pragma unroll
                    for (int q = KNN-2; q >= 0; --q)
                        if ((v > tv[q]) || (v == tv[q] && rk < tr[q])) pos = q;
                    #pragma unroll
                    for (int q = KNN-1; q > 0; --q)
                        if (q > pos) { tv[q] = tv[q-1]; ti[q] = ti[q-1]; tr[q] = tr[q-1]; }
                    #pragma unroll
                    for (int q = 0; q < KNN; ++q)
                        if (q == pos) { tv[q] = v; ti[q] = jn; tr[q] = rk; }
                }
            }
        }
    }

    // merge the two halves' sorted lists (reuse cs as staging)
    __syncthreads();
    float*    mv = cs;                       // [128][9]
    int*      mi = (int*)(cs + 128*KNN);
    unsigned* mr = (unsigned*)(cs + 2*128*KNN);
    if (h == 1) {
        #pragma unroll
        for (int q = 0; q < KNN; ++q) {
            mv[r*KNN + q] = tv[q];
            mi[r*KNN + q] = ti[q];
            mr[r*KNN + q] = tr[q];
        }
    }
    __syncthreads();
    if (h == 0 && row < NPTS) {
        int outi[KNN];
        int ia = 0, ib = 0;
        #pragma unroll
        for (int q = 0; q < KNN; ++q) {
            float    va = tv[ia],          vb = mv[r*KNN + ib];
            unsigned ra = tr[ia],          rb = mr[r*KNN + ib];
            int      ja = ti[ia],          jb = mi[r*KNN + ib];
            bool takeA = (va > vb) || (va == vb && (ra < rb || (ra == rb && ja < jb)));
            outi[q] = takeA ? ja : jb;
            if (takeA) ++ia; else ++ib;
        }
        #pragma unroll
        for (int q = 0; q < KNN; ++q) out_idx[(b*NPTS + row)*KNN + q] = outi[q];
    }
}

// ---------------- weight packing ----------------
// g_W[k*512 + row]; row<384: Wd_t (t=row>>7), row>=384: A = sum_t (Wc_t + Wd_t)
__global__ void prepW1_kernel(const float* __restrict__ w1, float* __restrict__ W) {
    int id = blockIdx.x * 256 + threadIdx.x;
    if (id >= 128*512) return;
    int k = id >> 9;        // 0..127
    int row = id & 511;
    float v;
    if (row < 384) {
        int t = row >> 7, o = row & 127;
        v = w1[(o*256 + 128 + k)*3 + t];
    } else {
        int o = row - 384;
        v = 0.f;
        #pragma unroll
        for (int t = 0; t < 3; ++t)
            v += w1[(o*256 + k)*3 + t] + w1[(o*256 + 128 + k)*3 + t];
    }
    W[k*512 + row] = v;
}

// g_W2t[j*128 + o] = w2[o][i][w],  j = w*128 + i
__global__ void prepW2_kernel(const float* __restrict__ w2, float* __restrict__ W2t) {
    int id = blockIdx.x * 256 + threadIdx.x;
    if (id >= 384*128) return;
    int o = id & 127, j = id >> 7;
    int i = j & 127, w = j >> 7;
    W2t[j*128 + o] = w2[(o*128 + i)*3 + w];
}

// ---------------- GEMM: P[p][row] = sum_k X[k][p] * W[k][row] ----------------
// grid (125, 4), block 256. dyn smem: Xs[128*128] + Ws[128*128]
__global__ void gemm_kernel(const float* __restrict__ X, const float* __restrict__ W,
                            float* __restrict__ P) {
    extern __shared__ float sm[];
    float* Xs = sm;            // [k][pl]
    float* Ws = sm + 128*128;  // [k][ol]
    const int p0 = blockIdx.x * 128;
    const int o0 = blockIdx.y * 128;
    const int tid = threadIdx.x;

    for (int i = tid; i < 128*128; i += 256) {
        int k = i >> 7, pl = i & 127;
        int p = p0 + pl;
        int b = p / NPTS;
        int n = p - b*NPTS;
        Xs[i] = X[(b*CDIM + k)*NPTS + n];
    }
    for (int i = tid; i < 128*128; i += 256) {
        int k = i >> 7, ol = i & 127;
        Ws[i] = W[k*512 + o0 + ol];
    }
    __syncthreads();

    const int to = tid & 15;
    const int tp = tid >> 4;
    float acc[8][8];
    #pragma unroll
    for (int u = 0; u < 8; ++u)
        #pragma unroll
        for (int v = 0; v < 8; ++v) acc[u][v] = 0.f;

    #pragma unroll 2
    for (int k = 0; k < 128; ++k) {
        float xv[8], wv[8];
        #pragma unroll
        for (int u = 0; u < 8; ++u) xv[u] = Xs[k*128 + tp + 16*u];
        #pragma unroll
        for (int v = 0; v < 8; ++v) wv[v] = Ws[k*128 + to + 16*v];
        #pragma unroll
        for (int u = 0; u < 8; ++u)
            #pragma unroll
            for (int v = 0; v < 8; ++v)
                acc[u][v] = fmaf(xv[u], wv[v], acc[u][v]);
    }

    #pragma unroll
    for (int u = 0; u < 8; ++u)
        #pragma unroll
        for (int v = 0; v < 8; ++v)
            P[(p0 + tp + 16*u)*512 + o0 + to + 16*v] = acc[u][v];
}

// ---------------- gather: y1[p][w*128+o] = A x_p - sum_t u_t[nbr(3w+t)] ----------------
__global__ void gather_kernel(const float* __restrict__ P, const int* __restrict__ idx,
                              float* __restrict__ y1) {
    int p = blockIdx.x * 4 + (threadIdx.x >> 7);
    int o = threadIdx.x & 127;
    int b = p / NPTS;
    int base = b * NPTS;
    const int* id = idx + p * KNN;
    float a = P[p*512 + 384 + o];
    float a0 = a, a1 = a, a2 = a;
    #pragma unroll
    for (int t = 0; t < 3; ++t) {
        a0 -= P[(base + id[0 + t])*512 + t*128 + o];
        a1 -= P[(base + id[3 + t])*512 + t*128 + o];
        a2 -= P[(base + id[6 + t])*512 + t*128 + o];
    }
    y1[p*384 +   0 + o] = a0;
    y1[p*384 + 128 + o] = a1;
    y1[p*384 + 256 + o] = a2;
}

// ---------------- BN stats: deterministic two-stage ----------------
__global__ void stats_s1(const float* __restrict__ y, int rows, float* __restrict__ part) {
    int c = threadIdx.x;
    float s = 0.f, s2 = 0.f;
    for (int r = blockIdx.x; r < rows; r += 256) {
        float v = y[r*128 + c];
        s += v;
        s2 = fmaf(v, v, s2);
    }
    part[blockIdx.x*128 + c] = s;
    part[256*128 + blockIdx.x*128 + c] = s2;
}
__global__ void stats_s2(const float* __restrict__ part, float* __restrict__ st) {
    int c = threadIdx.x;
    float s = 0.f, s2 = 0.f;
    for (int g = 0; g < 256; ++g) {
        s  += part[g*128 + c];
        s2 += part[256*128 + g*128 + c];
    }
    st[c] = s; st[128 + c] = s2;
}

// ---------------- fused BN1+ReLU+conv2: y2[p][o] = sum_j W2t[j][o] * relu(s*y1+c) ----------------
// grid 125, block 256. dyn smem: z[64*129] + Ws[64*128]
__global__ void conv2_kernel(const float* __restrict__ y1, const float* __restrict__ W2t,
                             const float* __restrict__ st, const float* __restrict__ g1,
                             const float* __restrict__ be1, float invcnt,
                             float* __restrict__ y2) {
    __shared__ float sA[128], cA[128];
    extern __shared__ float sm[];
    float* z  = sm;             // [k][pl], stride 129
    float* Ws = sm + 64*129;    // [k][o]
    const int tid = threadIdx.x;
    if (tid < 128) {
        float mean = st[tid] * invcnt;
        float var  = st[128 + tid] * invcnt - mean*mean;
        float s = g1[tid] * rsqrtf(var + 1e-5f);
        sA[tid] = s;
        cA[tid] = be1[tid] - mean * s;
    }
    const int p0 = blockIdx.x * 128;
    const int to = tid & 15;
    const int tp = tid >> 4;
    float acc[8][8];
    #pragma unroll
    for (int u = 0; u < 8; ++u)
        #pragma unroll
        for (int v = 0; v < 8; ++v) acc[u][v] = 0.f;

    for (int kc = 0; kc < 6; ++kc) {
        __syncthreads();
        for (int i = tid; i < 64*128; i += 256) {
            int k = i & 63, pl = i >> 6;
            int j = kc*64 + k;
            int ic = j & 127;
            float v = y1[(p0 + pl)*384 + j];
            z[k*129 + pl] = fmaxf(fmaf(v, sA[ic], cA[ic]), 0.f);
        }
        for (int i = tid; i < 64*128; i += 256) {
            int k = i >> 7, o = i & 127;
            Ws[k*128 + o] = W2t[(kc*64 + k)*128 + o];
        }
        __syncthreads();
        #pragma unroll 2
        for (int k = 0; k < 64; ++k) {
            float xv[8], wv[8];
            #pragma unroll
            for (int u = 0; u < 8; ++u) xv[u] = z[k*129 + tp + 16*u];
            #pragma unroll
            for (int v = 0; v < 8; ++v) wv[v] = Ws[k*128 + to + 16*v];
            #pragma unroll
            for (int u = 0; u < 8; ++u)
                #pragma unroll
                for (int v = 0; v < 8; ++v)
                    acc[u][v] = fmaf(xv[u], wv[v], acc[u][v]);
        }
    }
    #pragma unroll
    for (int u = 0; u < 8; ++u)
        #pragma unroll
        for (int v = 0; v < 8; ++v)
            y2[(p0 + tp + 16*u)*128 + to + 16*v] = acc[u][v];
}

// ---------------- final: BN2+ReLU both branches, combine, transpose to (B,C,N) ----------------
__global__ void final_kernel(const float* __restrict__ y2a, const float* __restrict__ y2b,
                             const float* __restrict__ sta, const float* __restrict__ stb,
                             const float* __restrict__ g2a, const float* __restrict__ be2a,
                             const float* __restrict__ g2b, const float* __restrict__ be2b,
                             const float* __restrict__ delta, float* __restrict__ out) {
    __shared__ float t[32][33];
    const int b  = blockIdx.z;
    const int n0 = blockIdx.x * 32;
    const int o0 = blockIdx.y * 32;
    const int tx = threadIdx.x, ty = threadIdx.y;
    const float dl = delta[0];
    const float ic = 1.f / (float)PTOT;

    int o = o0 + tx;
    float ma = sta[o]*ic, va = sta[128+o]*ic - ma*ma;
    float s_a = g2a[o]*rsqrtf(va + 1e-5f);
    float c_a = be2a[o] - ma*s_a;
    float mb = stb[o]*ic, vb = stb[128+o]*ic - mb*mb;
    float s_b = g2b[o]*rsqrtf(vb + 1e-5f);
    float c_b = be2b[o] - mb*s_b;

    #pragma unroll
    for (int q = 0; q < 4; ++q) {
        int n = n0 + ty + 8*q;
        float v = 0.f;
        if (n < NPTS) {
            int p = b*NPTS + n;
            float ra = fmaxf(fmaf(y2a[p*128 + o], s_a, c_a), 0.f);
            float rb = fmaxf(fmaf(y2b[p*128 + o], s_b, c_b), 0.f);
            v = fmaf(dl, rb, ra);
        }
        t[ty + 8*q][tx] = v;
    }
    __syncthreads();
    #pragma unroll
    for (int q = 0; q < 4; ++q) {
        int oo = o0 + ty + 8*q;
        int n  = n0 + tx;
        if (n < NPTS) out[(b*CDIM + oo)*NPTS + n] = t[tx][ty + 8*q];
    }
}

// ---------------- host ----------------
extern "C" void kernel_launch(void* const* d_in, const int* in_sizes, int n_in,
                              void* d_out, int out_size) {
    (void)in_sizes; (void)n_in; (void)out_size;
    const float* feats  = (const float*)d_in[0];
    const float* motion = (const float*)d_in[1];
    const float* w1_[2]  = { (const float*)d_in[2],  (const float*)d_in[10] };
    const float* g1_[2]  = { (const float*)d_in[4],  (const float*)d_in[12] };
    const float* be1_[2] = { (const float*)d_in[5],  (const float*)d_in[13] };
    const float* w2_[2]  = { (const float*)d_in[6],  (const float*)d_in[14] };
    const float* g2_[2]  = { (const float*)d_in[8],  (const float*)d_in[16] };
    const float* be2_[2] = { (const float*)d_in[9],  (const float*)d_in[17] };
    const float* delta   = (const float*)d_in[18];
    float* out = (float*)d_out;

    void *p_idx1, *p_idx2, *p_sqx, *p_sqm, *p_W, *p_W2t, *p_P, *p_y1, *p_y2a, *p_y2b;
    void *p_part, *p_st1, *p_st2a, *p_st2b;
    cudaGetSymbolAddress(&p_idx1, g_idx1);
    cudaGetSymbolAddress(&p_idx2, g_idx2);
    cudaGetSymbolAddress(&p_sqx,  g_sqx);
    cudaGetSymbolAddress(&p_sqm,  g_sqm);
    cudaGetSymbolAddress(&p_W,    g_W);
    cudaGetSymbolAddress(&p_W2t,  g_W2t);
    cudaGetSymbolAddress(&p_P,    g_P);
    cudaGetSymbolAddress(&p_y1,   g_y1);
    cudaGetSymbolAddress(&p_y2a,  g_y2a);
    cudaGetSymbolAddress(&p_y2b,  g_y2b);
    cudaGetSymbolAddress(&p_part, g_part);
    cudaGetSymbolAddress(&p_st1,  g_st1);
    cudaGetSymbolAddress(&p_st2a, g_st2a);
    cudaGetSymbolAddress(&p_st2b, g_st2b);

    const int KNN_SMEM   = (128*128 + 2*128*32 + 64) * 4;   // ~98.5 KB
    const int GEMM_SMEM  = (128*128 * 2) * 4;               // 128 KB
    const int CONV2_SMEM = (64*129 + 64*128) * 4;           // ~65 KB
    cudaFuncSetAttribute(knn_kernel,   cudaFuncAttributeMaxDynamicSharedMemorySize, KNN_SMEM);
    cudaFuncSetAttribute(gemm_kernel,  cudaFuncAttributeMaxDynamicSharedMemorySize, GEMM_SMEM);
    cudaFuncSetAttribute(conv2_kernel, cudaFuncAttributeMaxDynamicSharedMemorySize, CONV2_SMEM);

    // one warp per point
    sq_kernel<<<(PTOT*32 + 255)/256, 256>>>(feats,  (float*)p_sqx);
    sq_kernel<<<(PTOT*32 + 255)/256, 256>>>(motion, (float*)p_sqm);

    dim3 gK(16, BATCH);
    knn_kernel<<<gK, 256, KNN_SMEM>>>(feats,  (const float*)p_sqx, (int*)p_idx1);
    knn_kernel<<<gK, 256, KNN_SMEM>>>(motion, (const float*)p_sqm, (int*)p_idx2);

    void* idxs[2] = { p_idx1, p_idx2 };
    void* y2s[2]  = { p_y2a, p_y2b };
    void* st2s[2] = { p_st2a, p_st2b };

    for (int br = 0; br < 2; ++br) {
        prepW1_kernel<<<(128*512 + 255)/256, 256>>>(w1_[br], (float*)p_W);
        prepW2_kernel<<<(384*128 + 255)/256, 256>>>(w2_[br], (float*)p_W2t);
        gemm_kernel<<<dim3(125, 4), 256, GEMM_SMEM>>>(feats, (const float*)p_W, (float*)p_P);
        gather_kernel<<<PTOT/4, 512>>>((const float*)p_P, (const int*)idxs[br], (float*)p_y1);
        stats_s1<<<256, 128>>>((const float*)p_y1, PTOT*3, (float*)p_part);
        stats_s2<<<1, 128>>>((const float*)p_part, (float*)p_st1);
        conv2_kernel<<<125, 256, CONV2_SMEM>>>((const float*)p_y1, (const float*)p_W2t,
                                               (const float*)p_st1, g1_[br], be1_[br],
                                               1.0f/(float)(PTOT*3), (float*)y2s[br]);
        stats_s1<<<256, 128>>>((const float*)y2s[br], PTOT, (float*)p_part);
        stats_s2<<<1, 128>>>((const float*)p_part, (float*)st2s[br]);
    }

    final_kernel<<<dim3((NPTS + 31)/32, CDIM/32, BATCH), dim3(32, 8)>>>(
        (const float*)p_y2a, (const float*)p_y2b,
        (const float*)p_st2a, (const float*)p_st2b,
        g2_[0], be2_[0], g2_[1], be2_[1], delta, out);
}

// round 12
// speedup vs baseline: 2.1665x; 2.1665x over previous
#include <cuda_runtime.h>
#include <math.h>

#define BATCH 8
#define NPTS  2000
#define CDIM  128
#define KNN   9
#define PTOT  (BATCH*NPTS)   // 16000
#define TPAD  2048

// ---------------- scratch (device globals; no allocations allowed) ----------------
__device__ int   g_idx1[PTOT*KNN];
__device__ int   g_idx2[PTOT*KNN];
__device__ float g_sqx[PTOT];
__device__ float g_sqm[PTOT];
__device__ float g_pd[(size_t)BATCH*TPAD*TPAD];  // pairwise distance scratch (134MB)
__device__ float g_W[128*512];        // packed conv1 weights, layout [k][512]
__device__ float g_W2t[384*128];      // conv2 weights transposed, layout [j][128]
__device__ float g_P[PTOT*512];       // per-point precomputed features [p][512]
__device__ float g_y1[PTOT*384];      // conv1 output (pre-BN) [p][w*128+c]
__device__ float g_y2a[PTOT*128];     // conv2 output branch1 (pre-BN)
__device__ float g_y2b[PTOT*128];     // conv2 output branch2 (pre-BN)
__device__ float g_part[2*256*128];   // stats partials
__device__ float g_st1[256];          // [sum(128), sumsq(128)]
__device__ float g_st2a[256];
__device__ float g_st2b[256];

// ---------------- squared norms: XLA column-reduce shape (stride-32 tree) — LOCKED ----------------
__global__ void sq_kernel(const float* __restrict__ x, float* __restrict__ sq) {
    int w = (blockIdx.x * blockDim.x + threadIdx.x) >> 5;   // point index
    int lane = threadIdx.x & 31;
    if (w >= PTOT) return;
    int b = w / NPTS;
    int n = w - b * NPTS;
    const float* px = x + ((size_t)b * CDIM) * NPTS + n;
    float p = 0.f;
    #pragma unroll
    for (int k = 0; k < 4; ++k) {
        float v = px[(size_t)(lane + 32*k) * NPTS];
        p = fmaf(v, v, p);
    }
    #pragma unroll
    for (int off = 16; off; off >>= 1)
        p = __fadd_rn(p, __shfl_down_sync(0xffffffffu, p, off));
    if (lane == 0) sq[w] = p;
}

// ---------------- pairwise-distance GEMM (8x8 register tile) ----------------
// D[b][r][c] = RN( RN(2*inner - sq[r]) - sq[c] ), inner = serial ascending FFMA
// chain over d=0..127 (LOCKED bit pattern). grid (16,16,8), block 256.
// smem: Xs[64][128] + Cs[64][128] = 64KB, k-chunked (2 chunks of 64).
__global__ __launch_bounds__(256, 2)
void dist_kernel(const float* __restrict__ x, const float* __restrict__ sq,
                 float* __restrict__ D) {
    extern __shared__ float sm[];
    float* Xs = sm;            // [kk][r] 64x128
    float* Cs = sm + 64*128;   // [kk][c] 64x128
    const int b  = blockIdx.z;
    const int r0 = blockIdx.y * 128;
    const int c0 = blockIdx.x * 128;
    const int tid = threadIdx.x;
    const int tp = tid >> 4;       // 0..15 (row group)
    const int to = tid & 15;       // 0..15 (col group)

    float acc[8][8];
    #pragma unroll
    for (int u = 0; u < 8; ++u)
        #pragma unroll
        for (int v = 0; v < 8; ++v) acc[u][v] = 0.f;

    for (int kc = 0; kc < 2; ++kc) {
        __syncthreads();
        for (int i = tid; i < 64*128; i += 256) {
            int kk = i >> 7, rr = i & 127;
            int d = kc*64 + kk;
            int n = r0 + rr;
            Xs[i] = (n < NPTS) ? x[((size_t)(b*CDIM + d))*NPTS + n] : 0.f;
        }
        for (int i = tid; i < 64*128; i += 256) {
            int kk = i >> 7, cc = i & 127;
            int d = kc*64 + kk;
            int n = c0 + cc;
            Cs[i] = (n < NPTS) ? x[((size_t)(b*CDIM + d))*NPTS + n] : 0.f;
        }
        __syncthreads();
        const float4* Xs4 = (const float4*)Xs;
        const float4* Cs4 = (const float4*)Cs;
        #pragma unroll 4
        for (int kk = 0; kk < 64; ++kk) {
            float4 a0 = Xs4[kk*32 + tp];        // rows tp*4+0..3
            float4 a1 = Xs4[kk*32 + 16 + tp];   // rows 64+tp*4+0..3
            float4 b0 = Cs4[kk*32 + to];        // cols to*4+0..3
            float4 b1 = Cs4[kk*32 + 16 + to];   // cols 64+to*4+0..3
            float av[8] = {a0.x,a0.y,a0.z,a0.w, a1.x,a1.y,a1.z,a1.w};
            float bv[8] = {b0.x,b0.y,b0.z,b0.w, b1.x,b1.y,b1.z,b1.w};
            #pragma unroll
            for (int u = 0; u < 8; ++u)
                #pragma unroll
                for (int v = 0; v < 8; ++v)
                    acc[u][v] = fmaf(av[u], bv[v], acc[u][v]);
        }
    }

    // epilogue: LOCKED rounding v = RN(fmaf(2,inner,-sqr) - sqc)
    float sqr[8], sqc[8];
    #pragma unroll
    for (int u = 0; u < 8; ++u) {
        int rr = r0 + ((u < 4) ? tp*4 + u : 64 + tp*4 + u - 4);
        sqr[u] = (rr < NPTS) ? sq[b*NPTS + rr] : 0.f;
    }
    #pragma unroll
    for (int v = 0; v < 8; ++v) {
        int cc = c0 + ((v < 4) ? to*4 + v : 64 + to*4 + v - 4);
        sqc[v] = (cc < NPTS) ? sq[b*NPTS + cc] : 0.f;
    }
    #pragma unroll
    for (int u = 0; u < 8; ++u) {
        int rr = r0 + ((u < 4) ? tp*4 + u : 64 + tp*4 + u - 4);
        float4 o0, o1;
        o0.x = __fadd_rn(fmaf(2.f, acc[u][0], -sqr[u]), -sqc[0]);
        o0.y = __fadd_rn(fmaf(2.f, acc[u][1], -sqr[u]), -sqc[1]);
        o0.z = __fadd_rn(fmaf(2.f, acc[u][2], -sqr[u]), -sqc[2]);
        o0.w = __fadd_rn(fmaf(2.f, acc[u][3], -sqr[u]), -sqc[3]);
        o1.x = __fadd_rn(fmaf(2.f, acc[u][4], -sqr[u]), -sqc[4]);
        o1.y = __fadd_rn(fmaf(2.f, acc[u][5], -sqr[u]), -sqc[5]);
        o1.z = __fadd_rn(fmaf(2.f, acc[u][6], -sqr[u]), -sqc[6]);
        o1.w = __fadd_rn(fmaf(2.f, acc[u][7], -sqr[u]), -sqc[7]);
        float4* drow = (float4*)(D + ((size_t)b*TPAD + rr)*TPAD);
        drow[(c0 >> 2) + to]      = o0;
        drow[(c0 >> 2) + 16 + to] = o1;
    }
}

// ---------------- top-9 selection under the LOCKED total order ----------------
// key = (v asc-bits) << 17 | (63-rev6(j&63)) << 11 | (2047-j). Bigger key = better.
// One warp per row: lanes scan j ≡ lane (mod 32), keep sorted top-9, merge via
// 5 shfl_xor rounds. Total order (j unique) ⇒ unique top-9 ⇒ matches reference.
__device__ __forceinline__ void bubble9(unsigned long long* ks) {
    #pragma unroll
    for (int q = 8; q > 0; --q) {
        unsigned long long a = ks[q-1], c = ks[q];
        ks[q-1] = (a > c) ? a : c;
        ks[q]   = (a > c) ? c : a;
    }
}

__global__ void topk_kernel(const float* __restrict__ D, int* __restrict__ out_idx) {
    int gw = (blockIdx.x * blockDim.x + threadIdx.x) >> 5;
    int lane = threadIdx.x & 31;
    if (gw >= PTOT) return;
    int b = gw / NPTS, row = gw - b*NPTS;
    const float* Dr = D + ((size_t)b*TPAD + row)*TPAD;

    unsigned long long ks[KNN];
    #pragma unroll
    for (int q = 0; q < KNN; ++q) ks[q] = 0ull;   // below any real key

    for (int j = lane; j < NPTS; j += 32) {
        float v = Dr[j];
        unsigned u = __float_as_uint(v);
        unsigned fk = (u & 0x80000000u) ? ~u : (u | 0x80000000u);   // ascending
        unsigned rk = __brev((unsigned)(j & 63)) >> 26;             // rev6
        unsigned long long key = ((unsigned long long)fk << 17)
                               | ((unsigned long long)(63u - rk) << 11)
                               | (unsigned long long)(2047 - j);
        if (key > ks[KNN-1]) { ks[KNN-1] = key; bubble9(ks); }
    }

    #pragma unroll
    for (int off = 1; off < 32; off <<= 1) {
        unsigned long long pk[KNN];
        #pragma unroll
        for (int q = 0; q < KNN; ++q)
            pk[q] = __shfl_xor_sync(0xffffffffu, ks[q], off);
        #pragma unroll
        for (int t = 0; t < KNN; ++t) {
            if (pk[t] > ks[KNN-1]) { ks[KNN-1] = pk[t]; bubble9(ks); }
        }
    }

    if (lane == 0) {
        #pragma unroll
        for (int q = 0; q < KNN; ++q)
            out_idx[gw*KNN + q] = 2047 - (int)(ks[q] & 0x7FFull);
    }
}

// ---------------- weight packing ----------------
// g_W[k*512 + row]; row<384: Wd_t (t=row>>7), row>=384: A = sum_t (Wc_t + Wd_t)
__global__ void prepW1_kernel(const float* __restrict__ w1, float* __restrict__ W) {
    int id = blockIdx.x * 256 + threadIdx.x;
    if (id >= 128*512) return;
    int k = id >> 9;        // 0..127
    int row = id & 511;
    float v;
    if (row < 384) {
        int t = row >> 7, o = row & 127;
        v = w1[(o*256 + 128 + k)*3 + t];
    } else {
        int o = row - 384;
        v = 0.f;
        #pragma unroll
        for (int t = 0; t < 3; ++t)
            v += w1[(o*256 + k)*3 + t] + w1[(o*256 + 128 + k)*3 + t];
    }
    W[k*512 + row] = v;
}

// g_W2t[j*128 + o] = w2[o][i][w],  j = w*128 + i
__global__ void prepW2_kernel(const float* __restrict__ w2, float* __restrict__ W2t) {
    int id = blockIdx.x * 256 + threadIdx.x;
    if (id >= 384*128) return;
    int o = id & 127, j = id >> 7;
    int i = j & 127, w = j >> 7;
    W2t[j*128 + o] = w2[(o*128 + i)*3 + w];
}

// ---------------- GEMM: P[p][row] = sum_k X[k][p] * W[k][row] ----------------
// grid (125, 4), block 256. dyn smem: Xs[128*128] + Ws[128*128]
__global__ void gemm_kernel(const float* __restrict__ X, const float* __restrict__ W,
                            float* __restrict__ P) {
    extern __shared__ float sm[];
    float* Xs = sm;            // [k][pl]
    float* Ws = sm + 128*128;  // [k][ol]
    const int p0 = blockIdx.x * 128;
    const int o0 = blockIdx.y * 128;
    const int tid = threadIdx.x;

    for (int i = tid; i < 128*128; i += 256) {
        int k = i >> 7, pl = i & 127;
        int p = p0 + pl;
        int b = p / NPTS;
        int n = p - b*NPTS;
        Xs[i] = X[(b*CDIM + k)*NPTS + n];
    }
    for (int i = tid; i < 128*128; i += 256) {
        int k = i >> 7, ol = i & 127;
        Ws[i] = W[k*512 + o0 + ol];
    }
    __syncthreads();

    const int to = tid & 15;
    const int tp = tid >> 4;
    float acc[8][8];
    #pragma unroll
    for (int u = 0; u < 8; ++u)
        #pragma unroll
        for (int v = 0; v < 8; ++v) acc[u][v] = 0.f;

    #pragma unroll 2
    for (int k = 0; k < 128; ++k) {
        float xv[8], wv[8];
        #pragma unroll
        for (int u = 0; u < 8; ++u) xv[u] = Xs[k*128 + tp + 16*u];
        #pragma unroll
        for (int v = 0; v < 8; ++v) wv[v] = Ws[k*128 + to + 16*v];
        #pragma unroll
        for (int u = 0; u < 8; ++u)
            #pragma unroll
            for (int v = 0; v < 8; ++v)
                acc[u][v] = fmaf(xv[u], wv[v], acc[u][v]);
    }

    #pragma unroll
    for (int u = 0; u < 8; ++u)
        #pragma unroll
        for (int v = 0; v < 8; ++v)
            P[(p0 + tp + 16*u)*512 + o0 + to + 16*v] = acc[u][v];
}

// ---------------- gather: y1[p][w*128+o] = A x_p - sum_t u_t[nbr(3w+t)] ----------------
__global__ void gather_kernel(const float* __restrict__ P, const int* __restrict__ idx,
                              float* __restrict__ y1) {
    int p = blockIdx.x * 4 + (threadIdx.x >> 7);
    int o = threadIdx.x & 127;
    int b = p / NPTS;
    int base = b * NPTS;
    const int* id = idx + p * KNN;
    float a = P[p*512 + 384 + o];
    float a0 = a, a1 = a, a2 = a;
    #pragma unroll
    for (int t = 0; t < 3; ++t) {
        a0 -= P[(base + id[0 + t])*512 + t*128 + o];
        a1 -= P[(base + id[3 + t])*512 + t*128 + o];
        a2 -= P[(base + id[6 + t])*512 + t*128 + o];
    }
    y1[p*384 +   0 + o] = a0;
    y1[p*384 + 128 + o] = a1;
    y1[p*384 + 256 + o] = a2;
}

// ---------------- BN stats: deterministic two-stage ----------------
__global__ void stats_s1(const float* __restrict__ y, int rows, float* __restrict__ part) {
    int c = threadIdx.x;
    float s = 0.f, s2 = 0.f;
    for (int r = blockIdx.x; r < rows; r += 256) {
        float v = y[r*128 + c];
        s += v;
        s2 = fmaf(v, v, s2);
    }
    part[blockIdx.x*128 + c] = s;
    part[256*128 + blockIdx.x*128 + c] = s2;
}
__global__ void stats_s2(const float* __restrict__ part, float* __restrict__ st) {
    int c = threadIdx.x;
    float s = 0.f, s2 = 0.f;
    for (int g = 0; g < 256; ++g) {
        s  += part[g*128 + c];
        s2 += part[256*128 + g*128 + c];
    }
    st[c] = s; st[128 + c] = s2;
}

// ---------------- fused BN1+ReLU+conv2: y2[p][o] = sum_j W2t[j][o] * relu(s*y1+c) ----------------
// grid 125, block 256. dyn smem: z[64*129] + Ws[64*128]
__global__ void conv2_kernel(const float* __restrict__ y1, const float* __restrict__ W2t,
                             const float* __restrict__ st, const float* __restrict__ g1,
                             const float* __restrict__ be1, float invcnt,
                             float* __restrict__ y2) {
    __shared__ float sA[128], cA[128];
    extern __shared__ float sm[];
    float* z  = sm;             // [k][pl], stride 129
    float* Ws = sm + 64*129;    // [k][o]
    const int tid = threadIdx.x;
    if (tid < 128) {
        float mean = st[tid] * invcnt;
        float var  = st[128 + tid] * invcnt - mean*mean;
        float s = g1[tid] * rsqrtf(var + 1e-5f);
        sA[tid] = s;
        cA[tid] = be1[tid] - mean * s;
    }
    const int p0 = blockIdx.x * 128;
    const int to = tid & 15;
    const int tp = tid >> 4;
    float acc[8][8];
    #pragma unroll
    for (int u = 0; u < 8; ++u)
        #pragma unroll
        for (int v = 0; v < 8; ++v) acc[u][v] = 0.f;

    for (int kc = 0; kc < 6; ++kc) {
        __syncthreads();
        for (int i = tid; i < 64*128; i += 256) {
            int k = i & 63, pl = i >> 6;
            int j = kc*64 + k;
            int ic = j & 127;
            float v = y1[(p0 + pl)*384 + j];
            z[k*129 + pl] = fmaxf(fmaf(v, sA[ic], cA[ic]), 0.f);
        }
        for (int i = tid; i < 64*128; i += 256) {
            int k = i >> 7, o = i & 127;
            Ws[k*128 + o] = W2t[(kc*64 + k)*128 + o];
        }
        __syncthreads();
        #pragma unroll 2
        for (int k = 0; k < 64; ++k) {
            float xv[8], wv[8];
            #pragma unroll
            for (int u = 0; u < 8; ++u) xv[u] = z[k*129 + tp + 16*u];
            #pragma unroll
            for (int v = 0; v < 8; ++v) wv[v] = Ws[k*128 + to + 16*v];
            #pragma unroll
            for (int u = 0; u < 8; ++u)
                #pragma unroll
                for (int v = 0; v < 8; ++v)
                    acc[u][v] = fmaf(xv[u], wv[v], acc[u][v]);
        }
    }
    #pragma unroll
    for (int u = 0; u < 8; ++u)
        #pragma unroll
        for (int v = 0; v < 8; ++v)
            y2[(p0 + tp + 16*u)*128 + to + 16*v] = acc[u][v];
}

// ---------------- final: BN2+ReLU both branches, combine, transpose to (B,C,N) ----------------
__global__ void final_kernel(const float* __restrict__ y2a, const float* __restrict__ y2b,
                             const float* __restrict__ sta, const float* __restrict__ stb,
                             const float* __restrict__ g2a, const float* __restrict__ be2a,
                             const float* __restrict__ g2b, const float* __restrict__ be2b,
                             const float* __restrict__ delta, float* __restrict__ out) {
    __shared__ float t[32][33];
    const int b  = blockIdx.z;
    const int n0 = blockIdx.x * 32;
    const int o0 = blockIdx.y * 32;
    const int tx = threadIdx.x, ty = threadIdx.y;
    const float dl = delta[0];
    const float ic = 1.f / (float)PTOT;

    int o = o0 + tx;
    float ma = sta[o]*ic, va = sta[128+o]*ic - ma*ma;
    float s_a = g2a[o]*rsqrtf(va + 1e-5f);
    float c_a = be2a[o] - ma*s_a;
    float mb = stb[o]*ic, vb = stb[128+o]*ic - mb*mb;
    float s_b = g2b[o]*rsqrtf(vb + 1e-5f);
    float c_b = be2b[o] - mb*s_b;

    #pragma unroll
    for (int q = 0; q < 4; ++q) {
        int n = n0 + ty + 8*q;
        float v = 0.f;
        if (n < NPTS) {
            int p = b*NPTS + n;
            float ra = fmaxf(fmaf(y2a[p*128 + o], s_a, c_a), 0.f);
            float rb = fmaxf(fmaf(y2b[p*128 + o], s_b, c_b), 0.f);
            v = fmaf(dl, rb, ra);
        }
        t[ty + 8*q][tx] = v;
    }
    __syncthreads();
    #pragma unroll
    for (int q = 0; q < 4; ++q) {
        int oo = o0 + ty + 8*q;
        int n  = n0 + tx;
        if (n < NPTS) out[(b*CDIM + oo)*NPTS + n] = t[tx][ty + 8*q];
    }
}

// ---------------- host ----------------
extern "C" void kernel_launch(void* const* d_in, const int* in_sizes, int n_in,
                              void* d_out, int out_size) {
    (void)in_sizes; (void)n_in; (void)out_size;
    const float* feats  = (const float*)d_in[0];
    const float* motion = (const float*)d_in[1];
    const float* w1_[2]  = { (const float*)d_in[2],  (const float*)d_in[10] };
    const float* g1_[2]  = { (const float*)d_in[4],  (const float*)d_in[12] };
    const float* be1_[2] = { (const float*)d_in[5],  (const float*)d_in[13] };
    const float* w2_[2]  = { (const float*)d_in[6],  (const float*)d_in[14] };
    const float* g2_[2]  = { (const float*)d_in[8],  (const float*)d_in[16] };
    const float* be2_[2] = { (const float*)d_in[9],  (const float*)d_in[17] };
    const float* delta   = (const float*)d_in[18];
    float* out = (float*)d_out;

    void *p_idx1, *p_idx2, *p_sqx, *p_sqm, *p_pd, *p_W, *p_W2t, *p_P, *p_y1, *p_y2a, *p_y2b;
    void *p_part, *p_st1, *p_st2a, *p_st2b;
    cudaGetSymbolAddress(&p_idx1, g_idx1);
    cudaGetSymbolAddress(&p_idx2, g_idx2);
    cudaGetSymbolAddress(&p_sqx,  g_sqx);
    cudaGetSymbolAddress(&p_sqm,  g_sqm);
    cudaGetSymbolAddress(&p_pd,   g_pd);
    cudaGetSymbolAddress(&p_W,    g_W);
    cudaGetSymbolAddress(&p_W2t,  g_W2t);
    cudaGetSymbolAddress(&p_P,    g_P);
    cudaGetSymbolAddress(&p_y1,   g_y1);
    cudaGetSymbolAddress(&p_y2a,  g_y2a);
    cudaGetSymbolAddress(&p_y2b,  g_y2b);
    cudaGetSymbolAddress(&p_part, g_part);
    cudaGetSymbolAddress(&p_st1,  g_st1);
    cudaGetSymbolAddress(&p_st2a, g_st2a);
    cudaGetSymbolAddress(&p_st2b, g_st2b);

    const int DIST_SMEM  = (64*128*2) * 4;                  // 64 KB
    const int GEMM_SMEM  = (128*128 * 2) * 4;               // 128 KB
    const int CONV2_SMEM = (64*129 + 64*128) * 4;           // ~65 KB
    cudaFuncSetAttribute(dist_kernel,  cudaFuncAttributeMaxDynamicSharedMemorySize, DIST_SMEM);
    cudaFuncSetAttribute(gemm_kernel,  cudaFuncAttributeMaxDynamicSharedMemorySize, GEMM_SMEM);
    cudaFuncSetAttribute(conv2_kernel, cudaFuncAttributeMaxDynamicSharedMemorySize, CONV2_SMEM);

    // squared norms (one warp per point) — LOCKED arithmetic
    sq_kernel<<<(PTOT*32 + 255)/256, 256>>>(feats,  (float*)p_sqx);
    sq_kernel<<<(PTOT*32 + 255)/256, 256>>>(motion, (float*)p_sqm);

    // KNN #1: distance GEMM -> top-9
    dim3 gD(TPAD/128, TPAD/128, BATCH);   // (16,16,8)
    dist_kernel<<<gD, 256, DIST_SMEM>>>(feats, (const float*)p_sqx, (float*)p_pd);
    topk_kernel<<<(PTOT*32 + 255)/256, 256>>>((const float*)p_pd, (int*)p_idx1);
    // KNN #2 (reuses pd scratch; stream-ordered)
    dist_kernel<<<gD, 256, DIST_SMEM>>>(motion, (const float*)p_sqm, (float*)p_pd);
    topk_kernel<<<(PTOT*32 + 255)/256, 256>>>((const float*)p_pd, (int*)p_idx2);

    void* idxs[2] = { p_idx1, p_idx2 };
    void* y2s[2]  = { p_y2a, p_y2b };
    void* st2s[2] = { p_st2a, p_st2b };

    for (int br = 0; br < 2; ++br) {
        prepW1_kernel<<<(128*512 + 255)/256, 256>>>(w1_[br], (float*)p_W);
        prepW2_kernel<<<(384*128 + 255)/256, 256>>>(w2_[br], (float*)p_W2t);
        gemm_kernel<<<dim3(125, 4), 256, GEMM_SMEM>>>(feats, (const float*)p_W, (float*)p_P);
        gather_kernel<<<PTOT/4, 512>>>((const float*)p_P, (const int*)idxs[br], (float*)p_y1);
        stats_s1<<<256, 128>>>((const float*)p_y1, PTOT*3, (float*)p_part);
        stats_s2<<<1, 128>>>((const float*)p_part, (float*)p_st1);
        conv2_kernel<<<125, 256, CONV2_SMEM>>>((const float*)p_y1, (const float*)p_W2t,
                                               (const float*)p_st1, g1_[br], be1_[br],
                                               1.0f/(float)(PTOT*3), (float*)y2s[br]);
        stats_s1<<<256, 128>>>((const float*)y2s[br], PTOT, (float*)p_part);
        stats_s2<<<1, 128>>>((const float*)p_part, (float*)st2s[br]);
    }

    final_kernel<<<dim3((NPTS + 31)/32, CDIM/32, BATCH), dim3(32, 8)>>>(
        (const float*)p_y2a, (const float*)p_y2b,
        (const float*)p_st2a, (const float*)p_st2b,
        g2_[0], be2_[0], g2_[1], be2_[1], delta, out);
}